// round 12
// baseline (speedup 1.0000x reference)
#include <cuda_runtime.h>
#include <math.h>
#include <stdint.h>

#define N_NODES 2000
#define NFEAT   128
#define LB      128
#define TFEAT   36
#define FC1     256
#define DELTA_MIN 0.05f

// ---------------- scratch (device globals; no allocation) ----------------
__device__ float g_accP[25][FC1 * LB];     // split-K partials, [split][t*256 + k]
__device__ float g_Hs[LB * FC1];           // relu spatial hidden, [t][k] (tf32)
__device__ float g_Ht[LB * FC1];           // relu temporal hidden, [t][k] (tf32)
__device__ float g_U1[N_NODES * LB];       // U[:,:,i1]  [n][t]  (tf32)
__device__ float g_P [N_NODES * LB];       // U2 @ B^T   [m][f]

__device__ __forceinline__ float to_tf32(float x) {
    uint32_t u;
    asm("cvt.rna.tf32.f32 %0, %1;" : "=r"(u) : "f"(x));
    return __uint_as_float(u);
}
__device__ __forceinline__ void cp_async16(uint32_t dst, const void* src) {
    asm volatile("cp.async.ca.shared.global [%0], [%1], 16;" :: "r"(dst), "l"(src));
}
__device__ __forceinline__ void cp_async16z(uint32_t dst, const void* src, int ssize) {
    asm volatile("cp.async.ca.shared.global [%0], [%1], 16, %2;"
                 :: "r"(dst), "l"(src), "r"(ssize));
}
__device__ __forceinline__ void cp_async4(uint32_t dst, const void* src) {
    asm volatile("cp.async.ca.shared.global [%0], [%1], 4;" :: "r"(dst), "l"(src));
}

#define MMA_TF32(c, a, b)                                                          \
    asm volatile("mma.sync.aligned.m16n8k8.row.col.f32.tf32.tf32.f32 "             \
                 "{%0,%1,%2,%3},{%4,%5,%6,%7},{%8,%9},{%0,%1,%2,%3};"              \
                 : "+f"(c[0]), "+f"(c[1]), "+f"(c[2]), "+f"(c[3])                  \
                 : "r"(a[0]), "r"(a[1]), "r"(a[2]), "r"(a[3]), "r"(b[0]), "r"(b[1]))

// ---------------- kernel 1: spatial hidden via tf32 mma, split-K ----------
// grid (4 k-tiles of 64, 25 j-splits of 80), block 256 (8 warps: 4 t x 2 k)
__global__ __launch_bounds__(256) void k_hid_s(const float* __restrict__ li,
                                               const float* __restrict__ Ws1) {
    __shared__ float smA[128 * 20];   // [t][j-chunk 16], pad 20
    __shared__ float smB[64 * 17];    // [k][j-chunk 16], pad 17
    const int k0 = blockIdx.x * 64;
    const int j0 = blockIdx.y * 80;
    const int sp = blockIdx.y;
    const int tid = threadIdx.x;
    const int warp = tid >> 5, lane = tid & 31;
    const int wt = warp & 3;
    const int wc = warp >> 2;
    const int g = lane >> 2, tg = lane & 3;

    float acc[2][4][4];
#pragma unroll
    for (int i = 0; i < 2; i++)
#pragma unroll
        for (int j = 0; j < 4; j++)
#pragma unroll
            for (int q = 0; q < 4; q++) acc[i][j][q] = 0.f;

    for (int jb = 0; jb < 80; jb += 16) {
        __syncthreads();
#pragma unroll
        for (int it = 0; it < 2; it++) {
            int e = tid + it * 256;
            int row = e >> 2, j4 = (e & 3) * 4;
            *(float4*)&smA[row * 20 + j4] =
                *(const float4*)&li[row * N_NODES + j0 + jb + j4];
        }
#pragma unroll
        for (int it = 0; it < 4; it++) {
            int e = tid + it * 256;
            int jj = e >> 6, kk = e & 63;
            smB[kk * 17 + jj] = Ws1[(j0 + jb + jj) * FC1 + k0 + kk];
        }
        __syncthreads();
#pragma unroll
        for (int js = 0; js < 2; js++) {
            int j8 = js * 8;
            uint32_t af[2][4];
#pragma unroll
            for (int i = 0; i < 2; i++) {
                int base = (wt * 32 + i * 16) * 20 + j8;
                af[i][0] = __float_as_uint(smA[base + g * 20 + tg]);
                af[i][1] = __float_as_uint(smA[base + (g + 8) * 20 + tg]);
                af[i][2] = __float_as_uint(smA[base + g * 20 + tg + 4]);
                af[i][3] = __float_as_uint(smA[base + (g + 8) * 20 + tg + 4]);
            }
            uint32_t bf[4][2];
#pragma unroll
            for (int jt = 0; jt < 4; jt++) {
                int bb = (wc * 32 + jt * 8 + g) * 17 + j8 + tg;
                bf[jt][0] = __float_as_uint(smB[bb]);
                bf[jt][1] = __float_as_uint(smB[bb + 4]);
            }
#pragma unroll
            for (int i = 0; i < 2; i++)
#pragma unroll
                for (int jt = 0; jt < 4; jt++)
                    MMA_TF32(acc[i][jt], af[i], bf[jt]);
        }
    }

#pragma unroll
    for (int i = 0; i < 2; i++)
#pragma unroll
        for (int jt = 0; jt < 4; jt++) {
            int t = wt * 32 + i * 16 + g;
            int k = k0 + wc * 32 + jt * 8 + 2 * tg;
            *(float2*)&g_accP[sp][t * FC1 + k] =
                make_float2(acc[i][jt][0], acc[i][jt][1]);
            *(float2*)&g_accP[sp][(t + 8) * FC1 + k] =
                make_float2(acc[i][jt][2], acc[i][jt][3]);
        }
}

// ---------------- kernel 2: finalize hidden, store [t][k] tf32 ------------
__global__ void k_hid_fin(const float* __restrict__ tf, const float* __restrict__ Wt1,
                          const float* __restrict__ bs1, const float* __restrict__ bt1) {
    const int t = blockIdx.x;
    const int k = threadIdx.x;
    __shared__ float stf[TFEAT];
    if (k < TFEAT) stf[k] = tf[t * TFEAT + k];

    float hs = bs1[k];
#pragma unroll
    for (int s = 0; s < 25; s++) hs += g_accP[s][t * FC1 + k];
    g_Hs[t * FC1 + k] = to_tf32(fmaxf(hs, 0.f));

    __syncthreads();
    float a = bt1[k];
#pragma unroll
    for (int j = 0; j < TFEAT; j++)
        a += stf[j] * Wt1[j * FC1 + k];
    g_Ht[t * FC1 + k] = to_tf32(fmaxf(a, 0.f));
}

// ---------------- kernel 3: embed (fused W gather) + fused P --------------
// grid 250 (16 c' = 8 nodes each), block 256 (8 warps: 4 t-strips x 2 c-strips)
__global__ __launch_bounds__(256) void k_embed(
    const float* __restrict__ Ws2, const float* __restrict__ Wt2,
    const float* __restrict__ bs2, const float* __restrict__ bt2,
    const float* __restrict__ B,
    const int* __restrict__ idxp, const int* __restrict__ tdp) {

    __shared__ float smH[2][2][128 * 20];   // [buf][s][t*20+k] : 40.96 KB
    __shared__ float smW[2][2][16 * 20];    // [buf][s][cc*20+k]:  5.12 KB
    __shared__ float smU2[16 * 132];        // 8 valid rows + 8 dont-care: 8.45 KB
    __shared__ float smBs[16], smBt[16];

    const int idx = idxp[0];
    const int td  = tdp[0];
    const int i1  = (td >= 0) ? (idx - td) : idx;
    const int i2  = (td >= 0) ? idx        : (idx + td);

    const int c0  = blockIdx.x * 16;
    const int tid = threadIdx.x;
    const int warp = tid >> 5, lane = tid & 31;
    const int wt = warp & 3;          // t-strip of 32
    const int wc = warp >> 2;         // c-strip of 8
    const int g = lane >> 2, tg = lane & 3;

    if (tid < 16) {
        int cp = c0 + tid;
        int c = (cp >> 1) * NFEAT + ((cp & 1) ? i2 : i1);
        smBs[tid] = bs2[c];
        smBt[tid] = bt2[c];
    }

    const uint32_t baseH = (uint32_t)__cvta_generic_to_shared(&smH[0][0][0]);
    const uint32_t baseW = (uint32_t)__cvta_generic_to_shared(&smW[0][0][0]);

    // W gather coords: 512 elements/stage (16 cc x 16 kk x 2 s), 2 per thread.
    // e = tid + it*256 : s = e>>8, cc = (e&255)>>4, kk = e&15
    const float* wSrc[2];
    uint32_t     wDst[2];
#pragma unroll
    for (int it = 0; it < 2; it++) {
        int e  = tid + it * 256;
        int s  = e >> 8;
        int cc = (e & 255) >> 4;
        int kk = e & 15;
        int cp = c0 + cc;
        long c = (long)(cp >> 1) * NFEAT + ((cp & 1) ? i2 : i1);
        wSrc[it] = (s ? Wt2 : Ws2) + (long)kk * (N_NODES * NFEAT) + c;
        wDst[it] = (uint32_t)(s * 320 + cc * 20 + kk);
    }

#define EMB_ISSUE(st, b)                                                            \
    {                                                                               \
        int kc = (st) * 16;                                                         \
        _Pragma("unroll")                                                           \
        for (int it = 0; it < 4; it++) {                                            \
            int e = tid + it * 256;                                                 \
            int s = e >> 9, row = (e & 511) >> 2, k4 = (e & 3) * 4;                 \
            const float* src = (s ? g_Ht : g_Hs) + row * FC1 + kc + k4;             \
            cp_async16(baseH + ((b) * 5120 + s * 2560 + row * 20 + k4) * 4, src);   \
        }                                                                           \
        _Pragma("unroll")                                                           \
        for (int it = 0; it < 2; it++)                                              \
            cp_async4(baseW + ((b) * 640 + wDst[it]) * 4,                           \
                      wSrc[it] + (long)kc * (N_NODES * NFEAT));                     \
        asm volatile("cp.async.commit_group;");                                     \
    }

    float accS[2][4], accT[2][4];
#pragma unroll
    for (int i = 0; i < 2; i++)
#pragma unroll
        for (int q = 0; q < 4; q++) { accS[i][q] = 0.f; accT[i][q] = 0.f; }

    EMB_ISSUE(0, 0);
    for (int st = 0; st < 16; st++) {
        if (st < 15) EMB_ISSUE(st + 1, (st + 1) & 1);
        if (st < 15) { asm volatile("cp.async.wait_group 1;"); }
        else         { asm volatile("cp.async.wait_group 0;"); }
        __syncthreads();
        const float* sHs = &smH[st & 1][0][0];
        const float* sHt = &smH[st & 1][1][0];
        const float* sWs = &smW[st & 1][0][0];
        const float* sWt = &smW[st & 1][1][0];
#pragma unroll
        for (int ks = 0; ks < 2; ks++) {
            int k0 = ks * 8;
            uint32_t aS[2][4], aT[2][4];
#pragma unroll
            for (int i = 0; i < 2; i++) {
                int base = (wt * 32 + i * 16) * 20 + k0;
                aS[i][0] = __float_as_uint(sHs[base + g * 20 + tg]);
                aS[i][1] = __float_as_uint(sHs[base + (g + 8) * 20 + tg]);
                aS[i][2] = __float_as_uint(sHs[base + g * 20 + tg + 4]);
                aS[i][3] = __float_as_uint(sHs[base + (g + 8) * 20 + tg + 4]);
                aT[i][0] = __float_as_uint(sHt[base + g * 20 + tg]);
                aT[i][1] = __float_as_uint(sHt[base + (g + 8) * 20 + tg]);
                aT[i][2] = __float_as_uint(sHt[base + g * 20 + tg + 4]);
                aT[i][3] = __float_as_uint(sHt[base + (g + 8) * 20 + tg + 4]);
            }
            uint32_t bS[2], bT[2];
            {
                int bb = (wc * 8 + g) * 20 + k0 + tg;
                bS[0] = __float_as_uint(sWs[bb]);
                bS[1] = __float_as_uint(sWs[bb + 4]);
                bT[0] = __float_as_uint(sWt[bb]);
                bT[1] = __float_as_uint(sWt[bb + 4]);
            }
#pragma unroll
            for (int i = 0; i < 2; i++) {
                MMA_TF32(accS[i], aS[i], bS);
                MMA_TF32(accT[i], aT[i], bT);
            }
        }
        __syncthreads();
    }

    // ---- epilogue: relu sum; U1 -> global, U2 -> smem --------------------
#pragma unroll
    for (int i = 0; i < 2; i++)
#pragma unroll
        for (int q = 0; q < 4; q++) {
            int t   = wt * 32 + i * 16 + g + ((q & 2) ? 8 : 0);
            int col = wc * 8 + 2 * tg + (q & 1);
            int cp  = c0 + col;
            float v = fmaxf(accS[i][q] + smBs[col], 0.f)
                    + fmaxf(accT[i][q] + smBt[col], 0.f);
            if (cp & 1) {
                smU2[(col >> 1) * 132 + t] = v;
            } else {
                g_U1[(cp >> 1) * 128 + t] = to_tf32(v);
            }
        }
    __syncthreads();

    // ---- fused P = U2 @ B^T for this block's 8 nodes ---------------------
    // warp w -> f-strip of 16; mma rows 8-15 read dont-care smem, discarded.
    float* smBm = &smH[0][0][0];     // [128 f][36] = 4608 floats (cap 10240)
    float pacc[2][4];
#pragma unroll
    for (int j = 0; j < 2; j++)
#pragma unroll
        for (int q = 0; q < 4; q++) pacc[j][q] = 0.f;

    for (int gc = 0; gc < 128; gc += 32) {
        __syncthreads();
#pragma unroll
        for (int it = 0; it < 4; it++) {
            int e = tid + it * 256;
            int f = e >> 3, k4 = (e & 7) * 4;
            *(float4*)&smBm[f * 36 + k4] = *(const float4*)&B[f * 128 + gc + k4];
        }
        __syncthreads();
#pragma unroll
        for (int ks = 0; ks < 4; ks++) {
            int k0 = ks * 8;
            uint32_t af[4];
            af[0] = __float_as_uint(smU2[g * 132 + gc + k0 + tg]);
            af[1] = __float_as_uint(smU2[((g & 7) + 8) * 132 + gc + k0 + tg]);
            af[2] = __float_as_uint(smU2[g * 132 + gc + k0 + tg + 4]);
            af[3] = __float_as_uint(smU2[((g & 7) + 8) * 132 + gc + k0 + tg + 4]);
            uint32_t bf[2][2];
#pragma unroll
            for (int j = 0; j < 2; j++) {
                int bb = (warp * 16 + j * 8 + g) * 36 + k0 + tg;
                bf[j][0] = __float_as_uint(smBm[bb]);
                bf[j][1] = __float_as_uint(smBm[bb + 4]);
            }
#pragma unroll
            for (int j = 0; j < 2; j++)
                MMA_TF32(pacc[j], af, bf[j]);
        }
    }

    const int n0n = c0 >> 1;   // block * 8
#pragma unroll
    for (int j = 0; j < 2; j++) {
        int f = warp * 16 + j * 8 + 2 * tg;
        // only rows g (0..7) are valid nodes
        *(float2*)&g_P[(n0n + g) * 128 + f] = make_float2(pacc[j][0], pacc[j][1]);
    }
}

// ---------------- kernel 4: x = U1 @ P^T (tf32, cp.async 2-stage) ---------
__global__ __launch_bounds__(256) void k_gemm(float* __restrict__ out) {
    __shared__ float smA[2][128 * 36];
    __shared__ float smB[2][128 * 36];
    const int n0 = blockIdx.y * 128;
    const int m0 = blockIdx.x * 128;
    const int tid = threadIdx.x;
    const int warp = tid >> 5, lane = tid & 31;
    const int wn = warp & 3;
    const int wm = warp >> 2;
    const int g = lane >> 2, tg = lane & 3;
    const int lrow = tid >> 3, lkk = (tid & 7) * 4;

    const uint32_t baseA = (uint32_t)__cvta_generic_to_shared(&smA[0][0]);
    const uint32_t baseB = (uint32_t)__cvta_generic_to_shared(&smB[0][0]);

    float acc[2][8][4];
#pragma unroll
    for (int i = 0; i < 2; i++)
#pragma unroll
        for (int j = 0; j < 8; j++)
#pragma unroll
            for (int q = 0; q < 4; q++) acc[i][j][q] = 0.f;

#define GEMM_ISSUE(s, b)                                                            \
    {                                                                               \
        _Pragma("unroll")                                                           \
        for (int it = 0; it < 4; it++) {                                            \
            int row = lrow + it * 32;                                               \
            int gn = n0 + row, gm = m0 + row;                                       \
            int okA = (gn < N_NODES) ? 16 : 0;                                      \
            int okB = (gm < N_NODES) ? 16 : 0;                                      \
            int cn = (gn < N_NODES) ? gn : 0;                                       \
            int cm = (gm < N_NODES) ? gm : 0;                                       \
            cp_async16z(baseA + ((b) * 4608 + row * 36 + lkk) * 4,                  \
                        &g_U1[(long)cn * 128 + (s) * 32 + lkk], okA);               \
            cp_async16z(baseB + ((b) * 4608 + row * 36 + lkk) * 4,                  \
                        &g_P [(long)cm * 128 + (s) * 32 + lkk], okB);               \
        }                                                                           \
        asm volatile("cp.async.commit_group;");                                     \
    }

    GEMM_ISSUE(0, 0);
    for (int kc = 0; kc < 4; kc++) {
        if (kc < 3) GEMM_ISSUE(kc + 1, (kc + 1) & 1);
        if (kc < 3) { asm volatile("cp.async.wait_group 1;"); }
        else        { asm volatile("cp.async.wait_group 0;"); }
        __syncthreads();
        const float* sA = smA[kc & 1];
        const float* sB = smB[kc & 1];
#pragma unroll
        for (int ks = 0; ks < 4; ks++) {
            int k0 = ks * 8;
            uint32_t af[2][4];
#pragma unroll
            for (int i = 0; i < 2; i++) {
                int base = (wn * 32 + i * 16) * 36 + k0;
                af[i][0] = __float_as_uint(sA[base + g * 36 + tg]);
                af[i][1] = __float_as_uint(sA[base + (g + 8) * 36 + tg]);
                af[i][2] = __float_as_uint(sA[base + g * 36 + tg + 4]);
                af[i][3] = __float_as_uint(sA[base + (g + 8) * 36 + tg + 4]);
            }
            uint32_t bf[8][2];
#pragma unroll
            for (int j = 0; j < 8; j++) {
                int bb = (wm * 64 + j * 8 + g) * 36 + k0 + tg;
                bf[j][0] = __float_as_uint(sB[bb]);
                bf[j][1] = __float_as_uint(sB[bb + 4]);
            }
#pragma unroll
            for (int i = 0; i < 2; i++)
#pragma unroll
                for (int j = 0; j < 8; j++)
                    MMA_TF32(acc[i][j], af[i], bf[j]);
        }
        __syncthreads();
    }

#pragma unroll
    for (int i = 0; i < 2; i++) {
#pragma unroll
        for (int j = 0; j < 8; j++) {
            int n = n0 + wn * 32 + i * 16 + g;
            int m = m0 + wm * 64 + j * 8 + 2 * tg;
            if (m < N_NODES) {
                float2 v0, v1;
                v0.x = (acc[i][j][0] >= DELTA_MIN) ? acc[i][j][0] : 0.f;
                v0.y = (acc[i][j][1] >= DELTA_MIN) ? acc[i][j][1] : 0.f;
                v1.x = (acc[i][j][2] >= DELTA_MIN) ? acc[i][j][2] : 0.f;
                v1.y = (acc[i][j][3] >= DELTA_MIN) ? acc[i][j][3] : 0.f;
                if (n < N_NODES)     *(float2*)&out[(long)n * N_NODES + m] = v0;
                if (n + 8 < N_NODES) *(float2*)&out[(long)(n + 8) * N_NODES + m] = v1;
            }
        }
    }
}

// ---------------- kernel 5: in-place row softmax (float4) -----------------
__global__ void k_softmax(float* __restrict__ out) {
    const int row = blockIdx.x;
    float* p = out + (long)row * N_NODES;
    const int tid = threadIdx.x;
    const bool act = tid < 250;
    __shared__ float redM[8];
    __shared__ float redS[8];

    float4 v0, v1;
    float mx = -1e30f;
    if (act) {
        v0 = *(const float4*)&p[tid * 8];
        v1 = *(const float4*)&p[tid * 8 + 4];
        mx = fmaxf(fmaxf(fmaxf(v0.x, v0.y), fmaxf(v0.z, v0.w)),
                   fmaxf(fmaxf(v1.x, v1.y), fmaxf(v1.z, v1.w)));
    }
#pragma unroll
    for (int o = 16; o; o >>= 1) mx = fmaxf(mx, __shfl_xor_sync(0xFFFFFFFFu, mx, o));
    if ((tid & 31) == 0) redM[tid >> 5] = mx;
    __syncthreads();
    float gmax = redM[0];
#pragma unroll
    for (int w = 1; w < 8; w++) gmax = fmaxf(gmax, redM[w]);

    float s = 0.f;
    if (act) {
        v0.x = __expf(v0.x - gmax); v0.y = __expf(v0.y - gmax);
        v0.z = __expf(v0.z - gmax); v0.w = __expf(v0.w - gmax);
        v1.x = __expf(v1.x - gmax); v1.y = __expf(v1.y - gmax);
        v1.z = __expf(v1.z - gmax); v1.w = __expf(v1.w - gmax);
        s = v0.x + v0.y + v0.z + v0.w + v1.x + v1.y + v1.z + v1.w;
    }
#pragma unroll
    for (int o = 16; o; o >>= 1) s += __shfl_xor_sync(0xFFFFFFFFu, s, o);
    if ((tid & 31) == 0) redS[tid >> 5] = s;
    __syncthreads();
    float tot = 0.f;
#pragma unroll
    for (int w = 0; w < 8; w++) tot += redS[w];
    float inv = 1.f / tot;
    if (act) {
        v0.x *= inv; v0.y *= inv; v0.z *= inv; v0.w *= inv;
        v1.x *= inv; v1.y *= inv; v1.z *= inv; v1.w *= inv;
        *(float4*)&p[tid * 8]     = v0;
        *(float4*)&p[tid * 8 + 4] = v1;
    }
}

// ---------------- launch ---------------------------------------------------
extern "C" void kernel_launch(void* const* d_in, const int* in_sizes, int n_in,
                              void* d_out, int out_size) {
    const float* tf   = (const float*)d_in[0];
    const float* li   = (const float*)d_in[1];
    const float* Ws1  = (const float*)d_in[2];
    const float* bs1  = (const float*)d_in[3];
    const float* Ws2  = (const float*)d_in[4];
    const float* bs2  = (const float*)d_in[5];
    const float* Wt1  = (const float*)d_in[6];
    const float* bt1  = (const float*)d_in[7];
    const float* Wt2  = (const float*)d_in[8];
    const float* bt2  = (const float*)d_in[9];
    const float* B    = (const float*)d_in[10];
    const int*   idxp = (const int*)d_in[11];
    const int*   tdp  = (const int*)d_in[12];
    float* out = (float*)d_out;

    k_hid_s  <<<dim3(4, 25), 256>>>(li, Ws1);
    k_hid_fin<<<128, 256>>>(tf, Wt1, bs1, bt1);
    k_embed  <<<250, 256>>>(Ws2, Wt2, bs2, bt2, B, idxp, tdp);
    k_gemm   <<<dim3(16, 16), 256>>>(out);
    k_softmax<<<2000, 256>>>(out);
}

// round 13
// speedup vs baseline: 1.4431x; 1.4431x over previous
#include <cuda_runtime.h>
#include <math.h>
#include <stdint.h>

#define N_NODES 2000
#define NFEAT   128
#define LB      128
#define TFEAT   36
#define FC1     256
#define DELTA_MIN 0.05f

// ---------------- scratch (device globals; no allocation) ----------------
__device__ float g_accP[25][FC1 * LB];     // split-K partials, [split][t*256 + k]
__device__ float g_Hs[LB * FC1];           // relu spatial hidden, [t][k] (tf32)
__device__ float g_Ht[LB * FC1];           // relu temporal hidden, [t][k] (tf32)
__device__ float g_U1[N_NODES * LB];       // U[:,:,i1]  [n][t]  (tf32)
__device__ float g_P [N_NODES * LB];       // U2 @ B^T   [m][f]

__device__ __forceinline__ float to_tf32(float x) {
    uint32_t u;
    asm("cvt.rna.tf32.f32 %0, %1;" : "=r"(u) : "f"(x));
    return __uint_as_float(u);
}
__device__ __forceinline__ void cp_async16(uint32_t dst, const void* src) {
    asm volatile("cp.async.ca.shared.global [%0], [%1], 16;" :: "r"(dst), "l"(src));
}
__device__ __forceinline__ void cp_async16z(uint32_t dst, const void* src, int ssize) {
    asm volatile("cp.async.ca.shared.global [%0], [%1], 16, %2;"
                 :: "r"(dst), "l"(src), "r"(ssize));
}
__device__ __forceinline__ void cp_async4(uint32_t dst, const void* src) {
    asm volatile("cp.async.ca.shared.global [%0], [%1], 4;" :: "r"(dst), "l"(src));
}

#define MMA_TF32(c, a, b)                                                          \
    asm volatile("mma.sync.aligned.m16n8k8.row.col.f32.tf32.tf32.f32 "             \
                 "{%0,%1,%2,%3},{%4,%5,%6,%7},{%8,%9},{%0,%1,%2,%3};"              \
                 : "+f"(c[0]), "+f"(c[1]), "+f"(c[2]), "+f"(c[3])                  \
                 : "r"(a[0]), "r"(a[1]), "r"(a[2]), "r"(a[3]), "r"(b[0]), "r"(b[1]))

// ---------------- kernel 1: spatial hidden via tf32 mma, split-K ----------
// grid (4 k-tiles of 64, 25 j-splits of 80), block 256 (8 warps: 4 t x 2 k)
__global__ __launch_bounds__(256) void k_hid_s(const float* __restrict__ li,
                                               const float* __restrict__ Ws1) {
    __shared__ float smA[128 * 20];   // [t][j-chunk 16], pad 20
    __shared__ float smB[64 * 17];    // [k][j-chunk 16], pad 17
    const int k0 = blockIdx.x * 64;
    const int j0 = blockIdx.y * 80;
    const int sp = blockIdx.y;
    const int tid = threadIdx.x;
    const int warp = tid >> 5, lane = tid & 31;
    const int wt = warp & 3;
    const int wc = warp >> 2;
    const int g = lane >> 2, tg = lane & 3;

    float acc[2][4][4];
#pragma unroll
    for (int i = 0; i < 2; i++)
#pragma unroll
        for (int j = 0; j < 4; j++)
#pragma unroll
            for (int q = 0; q < 4; q++) acc[i][j][q] = 0.f;

    for (int jb = 0; jb < 80; jb += 16) {
        __syncthreads();
#pragma unroll
        for (int it = 0; it < 2; it++) {
            int e = tid + it * 256;
            int row = e >> 2, j4 = (e & 3) * 4;
            *(float4*)&smA[row * 20 + j4] =
                *(const float4*)&li[row * N_NODES + j0 + jb + j4];
        }
#pragma unroll
        for (int it = 0; it < 4; it++) {
            int e = tid + it * 256;
            int jj = e >> 6, kk = e & 63;
            smB[kk * 17 + jj] = Ws1[(j0 + jb + jj) * FC1 + k0 + kk];
        }
        __syncthreads();
#pragma unroll
        for (int js = 0; js < 2; js++) {
            int j8 = js * 8;
            uint32_t af[2][4];
#pragma unroll
            for (int i = 0; i < 2; i++) {
                int base = (wt * 32 + i * 16) * 20 + j8;
                af[i][0] = __float_as_uint(smA[base + g * 20 + tg]);
                af[i][1] = __float_as_uint(smA[base + (g + 8) * 20 + tg]);
                af[i][2] = __float_as_uint(smA[base + g * 20 + tg + 4]);
                af[i][3] = __float_as_uint(smA[base + (g + 8) * 20 + tg + 4]);
            }
            uint32_t bf[4][2];
#pragma unroll
            for (int jt = 0; jt < 4; jt++) {
                int bb = (wc * 32 + jt * 8 + g) * 17 + j8 + tg;
                bf[jt][0] = __float_as_uint(smB[bb]);
                bf[jt][1] = __float_as_uint(smB[bb + 4]);
            }
#pragma unroll
            for (int i = 0; i < 2; i++)
#pragma unroll
                for (int jt = 0; jt < 4; jt++)
                    MMA_TF32(acc[i][jt], af[i], bf[jt]);
        }
    }

#pragma unroll
    for (int i = 0; i < 2; i++)
#pragma unroll
        for (int jt = 0; jt < 4; jt++) {
            int t = wt * 32 + i * 16 + g;
            int k = k0 + wc * 32 + jt * 8 + 2 * tg;
            *(float2*)&g_accP[sp][t * FC1 + k] =
                make_float2(acc[i][jt][0], acc[i][jt][1]);
            *(float2*)&g_accP[sp][(t + 8) * FC1 + k] =
                make_float2(acc[i][jt][2], acc[i][jt][3]);
        }
}

// ---------------- kernel 2: finalize hidden, store [t][k] tf32 ------------
__global__ void k_hid_fin(const float* __restrict__ tf, const float* __restrict__ Wt1,
                          const float* __restrict__ bs1, const float* __restrict__ bt1) {
    const int t = blockIdx.x;
    const int k = threadIdx.x;
    __shared__ float stf[TFEAT];
    if (k < TFEAT) stf[k] = tf[t * TFEAT + k];

    float hs = bs1[k];
#pragma unroll
    for (int s = 0; s < 25; s++) hs += g_accP[s][t * FC1 + k];
    g_Hs[t * FC1 + k] = to_tf32(fmaxf(hs, 0.f));

    __syncthreads();
    float a = bt1[k];
#pragma unroll
    for (int j = 0; j < TFEAT; j++)
        a += stf[j] * Wt1[j * FC1 + k];
    g_Ht[t * FC1 + k] = to_tf32(fmaxf(a, 0.f));
}

// ---------------- kernel 3: embed (fused W gather, depth-3) + fused P -----
// grid 126 (32 c' = 16 nodes each), block 256 (8 warps: 4 t-strips x 2 c-strips)
__global__ __launch_bounds__(256) void k_embed(
    const float* __restrict__ Ws2, const float* __restrict__ Wt2,
    const float* __restrict__ bs2, const float* __restrict__ bt2,
    const float* __restrict__ B,
    const int* __restrict__ idxp, const int* __restrict__ tdp) {

    __shared__ float smH[3][2][128 * 20];   // [buf][s][t*20+k] : 61.44 KB
    __shared__ float smW[3][2][32 * 20];    // [buf][s][cc*20+k]: 15.36 KB
    __shared__ float smBs[32], smBt[32];

    const int idx = idxp[0];
    const int td  = tdp[0];
    const int i1  = (td >= 0) ? (idx - td) : idx;
    const int i2  = (td >= 0) ? idx        : (idx + td);

    const int c0  = blockIdx.x * 32;
    const int tid = threadIdx.x;
    const int warp = tid >> 5, lane = tid & 31;
    const int wt = warp & 3;          // t-strip of 32
    const int wc = warp >> 2;         // c-strip of 16
    const int g = lane >> 2, tg = lane & 3;

    if (tid < 32) {
        int cp = c0 + tid;
        float b1 = 0.f, b2 = 0.f;
        if (cp < 2 * N_NODES) {
            int c = (cp >> 1) * NFEAT + ((cp & 1) ? i2 : i1);
            b1 = bs2[c]; b2 = bt2[c];
        }
        smBs[tid] = b1; smBt[tid] = b2;
    }

    const uint32_t baseH = (uint32_t)__cvta_generic_to_shared(&smH[0][0][0]);
    const uint32_t baseW = (uint32_t)__cvta_generic_to_shared(&smW[0][0][0]);

    const float* wSrc[4];
    uint32_t     wDst[4];
#pragma unroll
    for (int it = 0; it < 4; it++) {
        int e  = tid + it * 256;
        int s  = e >> 9;
        int cc = (e & 511) >> 4;
        int kk = e & 15;
        int cp = c0 + cc; if (cp >= 2 * N_NODES) cp = 2 * N_NODES - 1;
        long c = (long)(cp >> 1) * NFEAT + ((cp & 1) ? i2 : i1);
        wSrc[it] = (s ? Wt2 : Ws2) + (long)kk * (N_NODES * NFEAT) + c;
        wDst[it] = (uint32_t)(s * 640 + cc * 20 + kk);
    }

#define EMB_ISSUE(st, b)                                                            \
    {                                                                               \
        int kc = (st) * 16;                                                         \
        _Pragma("unroll")                                                           \
        for (int it = 0; it < 4; it++) {                                            \
            int e = tid + it * 256;                                                 \
            int s = e >> 9, row = (e & 511) >> 2, k4 = (e & 3) * 4;                 \
            const float* src = (s ? g_Ht : g_Hs) + row * FC1 + kc + k4;             \
            cp_async16(baseH + ((b) * 5120 + s * 2560 + row * 20 + k4) * 4, src);   \
        }                                                                           \
        _Pragma("unroll")                                                           \
        for (int it = 0; it < 4; it++)                                              \
            cp_async4(baseW + ((b) * 1280 + wDst[it]) * 4,                          \
                      wSrc[it] + (long)kc * (N_NODES * NFEAT));                     \
        asm volatile("cp.async.commit_group;");                                     \
    }

    float accS[2][2][4], accT[2][2][4];
#pragma unroll
    for (int i = 0; i < 2; i++)
#pragma unroll
        for (int j = 0; j < 2; j++)
#pragma unroll
            for (int q = 0; q < 4; q++) { accS[i][j][q] = 0.f; accT[i][j][q] = 0.f; }

    EMB_ISSUE(0, 0);
    EMB_ISSUE(1, 1);
    for (int st = 0; st < 16; st++) {
        if (st < 14) {
            int nst = st + 2;
            EMB_ISSUE(nst, nst % 3);
            asm volatile("cp.async.wait_group 2;");
        } else if (st == 14) {
            asm volatile("cp.async.wait_group 1;");
        } else {
            asm volatile("cp.async.wait_group 0;");
        }
        __syncthreads();
        const int b = st % 3;
        const float* sHs = &smH[b][0][0];
        const float* sHt = &smH[b][1][0];
        const float* sWs = &smW[b][0][0];
        const float* sWt = &smW[b][1][0];
#pragma unroll
        for (int ks = 0; ks < 2; ks++) {
            int k0 = ks * 8;
            uint32_t aS[2][4], aT[2][4];
#pragma unroll
            for (int i = 0; i < 2; i++) {
                int base = (wt * 32 + i * 16) * 20 + k0;
                aS[i][0] = __float_as_uint(sHs[base + g * 20 + tg]);
                aS[i][1] = __float_as_uint(sHs[base + (g + 8) * 20 + tg]);
                aS[i][2] = __float_as_uint(sHs[base + g * 20 + tg + 4]);
                aS[i][3] = __float_as_uint(sHs[base + (g + 8) * 20 + tg + 4]);
                aT[i][0] = __float_as_uint(sHt[base + g * 20 + tg]);
                aT[i][1] = __float_as_uint(sHt[base + (g + 8) * 20 + tg]);
                aT[i][2] = __float_as_uint(sHt[base + g * 20 + tg + 4]);
                aT[i][3] = __float_as_uint(sHt[base + (g + 8) * 20 + tg + 4]);
            }
            uint32_t bS[2][2], bT[2][2];
#pragma unroll
            for (int j = 0; j < 2; j++) {
                int bb = (wc * 16 + j * 8 + g) * 20 + k0 + tg;
                bS[j][0] = __float_as_uint(sWs[bb]);
                bS[j][1] = __float_as_uint(sWs[bb + 4]);
                bT[j][0] = __float_as_uint(sWt[bb]);
                bT[j][1] = __float_as_uint(sWt[bb + 4]);
            }
#pragma unroll
            for (int i = 0; i < 2; i++)
#pragma unroll
                for (int j = 0; j < 2; j++) {
                    MMA_TF32(accS[i][j], aS[i], bS[j]);
                    MMA_TF32(accT[i][j], aT[i], bT[j]);
                }
        }
        __syncthreads();
    }

    // ---- epilogue: relu sum; U1 -> global, U2 -> smem (reuse smW) --------
    float* smU2 = &smW[0][0][0];     // [16 nodes][132 t] = 2112 floats (cap 3840)
#pragma unroll
    for (int i = 0; i < 2; i++)
#pragma unroll
        for (int j = 0; j < 2; j++)
#pragma unroll
            for (int q = 0; q < 4; q++) {
                int t   = wt * 32 + i * 16 + g + ((q & 2) ? 8 : 0);
                int col = wc * 16 + j * 8 + 2 * tg + (q & 1);
                int cp  = c0 + col;
                float v = fmaxf(accS[i][j][q] + smBs[col], 0.f)
                        + fmaxf(accT[i][j][q] + smBt[col], 0.f);
                if (cp & 1) {
                    smU2[(col >> 1) * 132 + t] = v;
                } else if (cp < 2 * N_NODES) {
                    g_U1[(cp >> 1) * 128 + t] = to_tf32(v);
                }
            }
    __syncthreads();

    // ---- fused P = U2 @ B^T for this block's 16 nodes --------------------
    float* smBm = &smH[0][0][0];     // [128 f][36] = 4608 floats (cap 15360)
    float pacc[2][4];
#pragma unroll
    for (int j = 0; j < 2; j++)
#pragma unroll
        for (int q = 0; q < 4; q++) pacc[j][q] = 0.f;

    for (int gc = 0; gc < 128; gc += 32) {
        __syncthreads();
#pragma unroll
        for (int it = 0; it < 4; it++) {
            int e = tid + it * 256;
            int f = e >> 3, k4 = (e & 7) * 4;
            *(float4*)&smBm[f * 36 + k4] = *(const float4*)&B[f * 128 + gc + k4];
        }
        __syncthreads();
#pragma unroll
        for (int ks = 0; ks < 4; ks++) {
            int k0 = ks * 8;
            uint32_t af[4];
            af[0] = __float_as_uint(smU2[g * 132 + gc + k0 + tg]);
            af[1] = __float_as_uint(smU2[(g + 8) * 132 + gc + k0 + tg]);
            af[2] = __float_as_uint(smU2[g * 132 + gc + k0 + tg + 4]);
            af[3] = __float_as_uint(smU2[(g + 8) * 132 + gc + k0 + tg + 4]);
            uint32_t bf[2][2];
#pragma unroll
            for (int j = 0; j < 2; j++) {
                int bb = (warp * 16 + j * 8 + g) * 36 + k0 + tg;
                bf[j][0] = __float_as_uint(smBm[bb]);
                bf[j][1] = __float_as_uint(smBm[bb + 4]);
            }
#pragma unroll
            for (int j = 0; j < 2; j++)
                MMA_TF32(pacc[j], af, bf[j]);
        }
    }

    const int n0n = c0 >> 1;
#pragma unroll
    for (int j = 0; j < 2; j++) {
        int f = warp * 16 + j * 8 + 2 * tg;
        if (n0n + g < N_NODES)
            *(float2*)&g_P[(n0n + g) * 128 + f] = make_float2(pacc[j][0], pacc[j][1]);
        if (n0n + g + 8 < N_NODES)
            *(float2*)&g_P[(n0n + g + 8) * 128 + f] = make_float2(pacc[j][2], pacc[j][3]);
    }
}

// ---------------- kernel 4: x = U1 @ P^T (tf32, cp.async 2-stage) ---------
__global__ __launch_bounds__(256) void k_gemm(float* __restrict__ out) {
    __shared__ float smA[2][128 * 36];
    __shared__ float smB[2][128 * 36];
    const int n0 = blockIdx.y * 128;
    const int m0 = blockIdx.x * 128;
    const int tid = threadIdx.x;
    const int warp = tid >> 5, lane = tid & 31;
    const int wn = warp & 3;
    const int wm = warp >> 2;
    const int g = lane >> 2, tg = lane & 3;
    const int lrow = tid >> 3, lkk = (tid & 7) * 4;

    const uint32_t baseA = (uint32_t)__cvta_generic_to_shared(&smA[0][0]);
    const uint32_t baseB = (uint32_t)__cvta_generic_to_shared(&smB[0][0]);

    float acc[2][8][4];
#pragma unroll
    for (int i = 0; i < 2; i++)
#pragma unroll
        for (int j = 0; j < 8; j++)
#pragma unroll
            for (int q = 0; q < 4; q++) acc[i][j][q] = 0.f;

#define GEMM_ISSUE(s, b)                                                            \
    {                                                                               \
        _Pragma("unroll")                                                           \
        for (int it = 0; it < 4; it++) {                                            \
            int row = lrow + it * 32;                                               \
            int gn = n0 + row, gm = m0 + row;                                       \
            int okA = (gn < N_NODES) ? 16 : 0;                                      \
            int okB = (gm < N_NODES) ? 16 : 0;                                      \
            int cn = (gn < N_NODES) ? gn : 0;                                       \
            int cm = (gm < N_NODES) ? gm : 0;                                       \
            cp_async16z(baseA + ((b) * 4608 + row * 36 + lkk) * 4,                  \
                        &g_U1[(long)cn * 128 + (s) * 32 + lkk], okA);               \
            cp_async16z(baseB + ((b) * 4608 + row * 36 + lkk) * 4,                  \
                        &g_P [(long)cm * 128 + (s) * 32 + lkk], okB);               \
        }                                                                           \
        asm volatile("cp.async.commit_group;");                                     \
    }

    GEMM_ISSUE(0, 0);
    for (int kc = 0; kc < 4; kc++) {
        if (kc < 3) GEMM_ISSUE(kc + 1, (kc + 1) & 1);
        if (kc < 3) { asm volatile("cp.async.wait_group 1;"); }
        else        { asm volatile("cp.async.wait_group 0;"); }
        __syncthreads();
        const float* sA = smA[kc & 1];
        const float* sB = smB[kc & 1];
#pragma unroll
        for (int ks = 0; ks < 4; ks++) {
            int k0 = ks * 8;
            uint32_t af[2][4];
#pragma unroll
            for (int i = 0; i < 2; i++) {
                int base = (wn * 32 + i * 16) * 36 + k0;
                af[i][0] = __float_as_uint(sA[base + g * 36 + tg]);
                af[i][1] = __float_as_uint(sA[base + (g + 8) * 36 + tg]);
                af[i][2] = __float_as_uint(sA[base + g * 36 + tg + 4]);
                af[i][3] = __float_as_uint(sA[base + (g + 8) * 36 + tg + 4]);
            }
            uint32_t bf[8][2];
#pragma unroll
            for (int j = 0; j < 8; j++) {
                int bb = (wm * 64 + j * 8 + g) * 36 + k0 + tg;
                bf[j][0] = __float_as_uint(sB[bb]);
                bf[j][1] = __float_as_uint(sB[bb + 4]);
            }
#pragma unroll
            for (int i = 0; i < 2; i++)
#pragma unroll
                for (int j = 0; j < 8; j++)
                    MMA_TF32(acc[i][j], af[i], bf[j]);
        }
        __syncthreads();
    }

#pragma unroll
    for (int i = 0; i < 2; i++) {
#pragma unroll
        for (int j = 0; j < 8; j++) {
            int n = n0 + wn * 32 + i * 16 + g;
            int m = m0 + wm * 64 + j * 8 + 2 * tg;
            if (m < N_NODES) {
                float2 v0, v1;
                v0.x = (acc[i][j][0] >= DELTA_MIN) ? acc[i][j][0] : 0.f;
                v0.y = (acc[i][j][1] >= DELTA_MIN) ? acc[i][j][1] : 0.f;
                v1.x = (acc[i][j][2] >= DELTA_MIN) ? acc[i][j][2] : 0.f;
                v1.y = (acc[i][j][3] >= DELTA_MIN) ? acc[i][j][3] : 0.f;
                if (n < N_NODES)     *(float2*)&out[(long)n * N_NODES + m] = v0;
                if (n + 8 < N_NODES) *(float2*)&out[(long)(n + 8) * N_NODES + m] = v1;
            }
        }
    }
}

// ---------------- kernel 5: in-place row softmax (float4) -----------------
__global__ void k_softmax(float* __restrict__ out) {
    const int row = blockIdx.x;
    float* p = out + (long)row * N_NODES;
    const int tid = threadIdx.x;
    const bool act = tid < 250;
    __shared__ float redM[8];
    __shared__ float redS[8];

    float4 v0, v1;
    float mx = -1e30f;
    if (act) {
        v0 = *(const float4*)&p[tid * 8];
        v1 = *(const float4*)&p[tid * 8 + 4];
        mx = fmaxf(fmaxf(fmaxf(v0.x, v0.y), fmaxf(v0.z, v0.w)),
                   fmaxf(fmaxf(v1.x, v1.y), fmaxf(v1.z, v1.w)));
    }
#pragma unroll
    for (int o = 16; o; o >>= 1) mx = fmaxf(mx, __shfl_xor_sync(0xFFFFFFFFu, mx, o));
    if ((tid & 31) == 0) redM[tid >> 5] = mx;
    __syncthreads();
    float gmax = redM[0];
#pragma unroll
    for (int w = 1; w < 8; w++) gmax = fmaxf(gmax, redM[w]);

    float s = 0.f;
    if (act) {
        v0.x = __expf(v0.x - gmax); v0.y = __expf(v0.y - gmax);
        v0.z = __expf(v0.z - gmax); v0.w = __expf(v0.w - gmax);
        v1.x = __expf(v1.x - gmax); v1.y = __expf(v1.y - gmax);
        v1.z = __expf(v1.z - gmax); v1.w = __expf(v1.w - gmax);
        s = v0.x + v0.y + v0.z + v0.w + v1.x + v1.y + v1.z + v1.w;
    }
#pragma unroll
    for (int o = 16; o; o >>= 1) s += __shfl_xor_sync(0xFFFFFFFFu, s, o);
    if ((tid & 31) == 0) redS[tid >> 5] = s;
    __syncthreads();
    float tot = 0.f;
#pragma unroll
    for (int w = 0; w < 8; w++) tot += redS[w];
    float inv = 1.f / tot;
    if (act) {
        v0.x *= inv; v0.y *= inv; v0.z *= inv; v0.w *= inv;
        v1.x *= inv; v1.y *= inv; v1.z *= inv; v1.w *= inv;
        *(float4*)&p[tid * 8]     = v0;
        *(float4*)&p[tid * 8 + 4] = v1;
    }
}

// ---------------- launch ---------------------------------------------------
extern "C" void kernel_launch(void* const* d_in, const int* in_sizes, int n_in,
                              void* d_out, int out_size) {
    const float* tf   = (const float*)d_in[0];
    const float* li   = (const float*)d_in[1];
    const float* Ws1  = (const float*)d_in[2];
    const float* bs1  = (const float*)d_in[3];
    const float* Ws2  = (const float*)d_in[4];
    const float* bs2  = (const float*)d_in[5];
    const float* Wt1  = (const float*)d_in[6];
    const float* bt1  = (const float*)d_in[7];
    const float* Wt2  = (const float*)d_in[8];
    const float* bt2  = (const float*)d_in[9];
    const float* B    = (const float*)d_in[10];
    const int*   idxp = (const int*)d_in[11];
    const int*   tdp  = (const int*)d_in[12];
    float* out = (float*)d_out;

    k_hid_s  <<<dim3(4, 25), 256>>>(li, Ws1);
    k_hid_fin<<<128, 256>>>(tf, Wt1, bs1, bt1);
    k_embed  <<<126, 256>>>(Ws2, Wt2, bs2, bt2, B, idxp, tdp);
    k_gemm   <<<dim3(16, 16), 256>>>(out);
    k_softmax<<<2000, 256>>>(out);
}